// round 16
// baseline (speedup 1.0000x reference)
#include <cuda_runtime.h>
#include <cuda_fp16.h>
#include <cstdint>
#include <math.h>

#define D_MODEL 1024
#define NH      16
#define DK      64
#define BATCH   2
#define SEQ     2048
#define M_TOT   (BATCH * SEQ)   // 4096
#define MM      (D_MODEL * D_MODEL)

// ---------------- scratch (static device memory; no allocations) ----------------
__device__ __half g_xh[M_TOT * D_MODEL];   // x split hi
__device__ __half g_xl[M_TOT * D_MODEL];   // x split lo
__device__ __half g_w [4 * MM];            // weights, single fp16
__device__ __half g_qh[M_TOT * D_MODEL];   // q split
__device__ __half g_ql[M_TOT * D_MODEL];
__device__ __half g_k [M_TOT * D_MODEL];   // k single
__device__ __half g_v [M_TOT * D_MODEL];   // v single
__device__ __half g_ch[M_TOT * D_MODEL];   // ctx single

// ================= helpers =================
static __device__ __forceinline__ uint32_t smem_to_u32(const void* p) {
    uint32_t a;
    asm("{ .reg .u64 t; cvta.to.shared.u64 t, %1; cvt.u32.u64 %0, t; }" : "=r"(a) : "l"(p));
    return a;
}
static __device__ __forceinline__ void cp_async16(uint32_t saddr, const void* gaddr) {
    asm volatile("cp.async.cg.shared.global [%0], [%1], 16;" :: "r"(saddr), "l"(gaddr));
}
#define CP_COMMIT() asm volatile("cp.async.commit_group;" ::: "memory")
#define CP_WAIT0()  asm volatile("cp.async.wait_group 0;" ::: "memory")
#define CP_WAIT1()  asm volatile("cp.async.wait_group 1;" ::: "memory")

static __device__ __forceinline__ void ldm_x4(uint32_t* r, uint32_t addr) {
    asm volatile("ldmatrix.sync.aligned.m8n8.x4.shared.b16 {%0,%1,%2,%3}, [%4];"
                 : "=r"(r[0]), "=r"(r[1]), "=r"(r[2]), "=r"(r[3]) : "r"(addr));
}
static __device__ __forceinline__ void ldm_x4_trans(uint32_t* r, uint32_t addr) {
    asm volatile("ldmatrix.sync.aligned.m8n8.x4.trans.shared.b16 {%0,%1,%2,%3}, [%4];"
                 : "=r"(r[0]), "=r"(r[1]), "=r"(r[2]), "=r"(r[3]) : "r"(addr));
}
static __device__ __forceinline__ void mma_f16(float* d, const uint32_t* a,
                                               uint32_t b0, uint32_t b1) {
    asm volatile(
        "mma.sync.aligned.m16n8k16.row.col.f32.f16.f16.f32 "
        "{%0,%1,%2,%3}, {%4,%5,%6,%7}, {%8,%9}, {%0,%1,%2,%3};"
        : "+f"(d[0]), "+f"(d[1]), "+f"(d[2]), "+f"(d[3])
        : "r"(a[0]), "r"(a[1]), "r"(a[2]), "r"(a[3]), "r"(b0), "r"(b1));
}
static __device__ __forceinline__ float ex2f(float x) {
    float r;
    asm("ex2.approx.ftz.f32 %0, %1;" : "=f"(r) : "f"(x));
    return r;
}
static __device__ __forceinline__ uint32_t pk_f16(float x, float y) {
    __half2 t = __floats2half2_rn(x, y);
    return *(uint32_t*)&t;
}

// ================= fused convert: W -> fp16 single; x -> fp16 split ==========
__global__ void __launch_bounds__(256) cvt_all(const float* __restrict__ x,
                                               const float* __restrict__ Wq,
                                               const float* __restrict__ Wk,
                                               const float* __restrict__ Wv,
                                               const float* __restrict__ Wo) {
    const int y = blockIdx.y;
    int i = (blockIdx.x * 256 + threadIdx.x) * 4;
    if (y < 4) {
        if (i >= MM) return;
        const float* src = (y == 0) ? Wq : (y == 1) ? Wk : (y == 2) ? Wv : Wo;
        __half* w = g_w + (size_t)y * MM;
        float4 v = *(const float4*)(src + i);
        *(__half2*)(w + i)     = __floats2half2_rn(v.x, v.y);
        *(__half2*)(w + i + 2) = __floats2half2_rn(v.z, v.w);
    } else {
        if (i >= M_TOT * D_MODEL) return;
        float4 v = *(const float4*)(x + i);
        __half h0 = __float2half_rn(v.x), h1 = __float2half_rn(v.y);
        __half h2 = __float2half_rn(v.z), h3 = __float2half_rn(v.w);
        *(__half2*)(g_xh + i)     = __half2(h0, h1);
        *(__half2*)(g_xh + i + 2) = __half2(h2, h3);
        *(__half2*)(g_xl + i) = __floats2half2_rn(v.x - __half2float(h0),
                                                  v.y - __half2float(h1));
        *(__half2*)(g_xl + i + 2) = __floats2half2_rn(v.z - __half2float(h2),
                                                      v.w - __half2float(h3));
    }
}

// ================= HMMA fp16 GEMM: 2-term when AlOpt, else 1-term ============
// K-chunks of 64 (NCHUNK 16); rows at 144B stride (conflict-free ldmatrix/STS).
// 3-stage cp.async ring with wait_group 1 (2 loads in flight, no full drain).
#define TSTRIDE_B 144
#define TILE_B    (128 * TSTRIDE_B)      // 18432
#define STAGE_B   (3 * TILE_B)           // 55296: Ah, Al, W
#define GEMM_SMEM (3 * STAGE_B)          // 165888 (1 CTA/SM)
#define NCHUNK    16

__global__ void __launch_bounds__(256, 1)
gemm_tc(const __half* __restrict__ Ah, const __half* __restrict__ AlOpt,
        const __half* __restrict__ W0,
        float* Cf,
        __half* H0, __half* L0,
        __half* H1, __half* L1,
        __half* H2, __half* L2) {
    extern __shared__ char smem[];
    const uint32_t sb = smem_to_u32(smem);
    const int tid  = threadIdx.x;
    const int wid  = tid >> 5;
    const int lane = tid & 31;
    const int z  = blockIdx.z;
    const int m0 = blockIdx.y * 128;
    const int n0 = blockIdx.x * 128;

    // lo term only on the q path (z==0); k/v/out-proj are 1-term
    const __half* Al = (z == 0) ? AlOpt : nullptr;
    const __half* Wz = W0 + (size_t)z * MM;
    __half* Hz = (z == 0) ? H0 : (z == 1) ? H1 : H2;
    __half* Lz = (z == 0) ? L0 : (z == 1) ? L1 : L2;

    const int seg = tid & 7;     // 16B segment within 128B row
    const int r0  = tid >> 3;    // 0..31

    auto load_chunk = [&](int kc, int s) {
        const uint32_t sbase = sb + s * STAGE_B;
        const int ke = kc * 64 + seg * 8;
#pragma unroll
        for (int j = 0; j < 4; j++) {
            const int row = r0 + j * 32;
            const uint32_t soff = row * TSTRIDE_B + seg * 16;
            cp_async16(sbase + 0 * TILE_B + soff, Ah + (size_t)(m0 + row) * D_MODEL + ke);
            if (Al)
                cp_async16(sbase + 1 * TILE_B + soff, Al + (size_t)(m0 + row) * D_MODEL + ke);
            cp_async16(sbase + 2 * TILE_B + soff, Wz + (size_t)(n0 + row) * D_MODEL + ke);
        }
    };

    const int wm = wid >> 2;
    const int wn = wid & 3;
    const uint32_t aRowOff = (uint32_t)((wm * 64 + (lane & 15)) * TSTRIDE_B + (lane >> 4) * 16);
    const int g = lane >> 3;
    const uint32_t bRowOff = (uint32_t)((wn * 32 + (g >> 1) * 8 + (lane & 7)) * TSTRIDE_B + (g & 1) * 16);

    float acc[4][4][4];
#pragma unroll
    for (int i = 0; i < 4; i++)
#pragma unroll
        for (int j = 0; j < 4; j++)
#pragma unroll
            for (int k = 0; k < 4; k++) acc[i][j][k] = 0.0f;

    load_chunk(0, 0);
    CP_COMMIT();
    load_chunk(1, 1);
    CP_COMMIT();

    for (int c = 0; c < NCHUNK; c++) {
        const int s = c % 3;
        CP_WAIT1();            // chunk c landed; chunk c+1 may still be in flight
        __syncthreads();       // also: all warps done computing stage (c-1)%3
        if (c + 2 < NCHUNK) { load_chunk(c + 2, (c + 2) % 3); CP_COMMIT(); }

        const uint32_t stage = sb + s * STAGE_B;
        const uint32_t ahB = stage + aRowOff;
        const uint32_t alB = ahB + TILE_B;
        const uint32_t wB  = stage + 2 * TILE_B + bRowOff;

#pragma unroll
        for (int kk = 0; kk < 4; kk++) {
            const uint32_t ka = kk * 32;
            uint32_t ahf[4][4], whf[2][4];
#pragma unroll
            for (int mf = 0; mf < 4; mf++)
                ldm_x4(ahf[mf], ahB + mf * (16 * TSTRIDE_B) + ka);
#pragma unroll
            for (int p = 0; p < 2; p++)
                ldm_x4(whf[p], wB + p * (16 * TSTRIDE_B) + ka);

#pragma unroll
            for (int mf = 0; mf < 4; mf++)
#pragma unroll
                for (int nf = 0; nf < 4; nf++) {
                    const int p = nf >> 1, h = (nf & 1) * 2;
                    mma_f16(acc[mf][nf], ahf[mf], whf[p][h], whf[p][h + 1]);
                }
            if (Al) {
                uint32_t alf[4][4];
#pragma unroll
                for (int mf = 0; mf < 4; mf++)
                    ldm_x4(alf[mf], alB + mf * (16 * TSTRIDE_B) + ka);
#pragma unroll
                for (int mf = 0; mf < 4; mf++)
#pragma unroll
                    for (int nf = 0; nf < 4; nf++) {
                        const int p = nf >> 1, h = (nf & 1) * 2;
                        mma_f16(acc[mf][nf], alf[mf], whf[p][h], whf[p][h + 1]);
                    }
            }
        }
    }

    __syncthreads();
    const int rr = lane >> 2;
    const int cc = (lane & 3) * 2;
#pragma unroll
    for (int mf = 0; mf < 4; mf++) {
#pragma unroll
        for (int nf = 0; nf < 4; nf++) {
            const size_t row = (size_t)(m0 + wm * 64 + mf * 16 + rr);
            const int col = n0 + wn * 32 + nf * 8 + cc;
            if (Cf) {
                float* cp = Cf + row * D_MODEL + col;
                *(float2*)cp                 = make_float2(acc[mf][nf][0], acc[mf][nf][1]);
                *(float2*)(cp + 8 * D_MODEL) = make_float2(acc[mf][nf][2], acc[mf][nf][3]);
            } else if (Lz) {   // split fp16 output (q)
#pragma unroll
                for (int hh = 0; hh < 2; hh++) {
                    float a0 = acc[mf][nf][hh * 2 + 0];
                    float a1 = acc[mf][nf][hh * 2 + 1];
                    __half h0 = __float2half_rn(a0);
                    __half h1 = __float2half_rn(a1);
                    size_t off = (row + hh * 8) * D_MODEL + col;
                    *(__half2*)(Hz + off) = __half2(h0, h1);
                    *(__half2*)(Lz + off) = __floats2half2_rn(a0 - __half2float(h0),
                                                              a1 - __half2float(h1));
                }
            } else {            // single fp16 output (k, v)
#pragma unroll
                for (int hh = 0; hh < 2; hh++) {
                    size_t off = (row + hh * 8) * D_MODEL + col;
                    *(__half2*)(Hz + off) = __floats2half2_rn(acc[mf][nf][hh * 2 + 0],
                                                              acc[mf][nf][hh * 2 + 1]);
                }
            }
        }
    }
}

// ================= HMMA flash attention (Q 2-term, P 1-term, causal) =========
#define KSTR 144
#define QTILE_B  (128 * KSTR)
#define KVTILE_B (64 * KSTR)
#define KVSTAGE_B (2 * KVTILE_B)        // K, V
#define FLASH_SMEM (2 * QTILE_B + 2 * KVSTAGE_B)   // 73728
#define SCL 0.18033688f                 // 0.125 * log2(e)

__global__ void __launch_bounds__(256, 1) flash_tc() {
    extern __shared__ char smf[];
    const uint32_t sb = smem_to_u32(smf);
    const uint32_t sQh = sb;
    const uint32_t sQl = sb + QTILE_B;
    const int tid  = threadIdx.x;
    const int wid  = tid >> 5;
    const int lane = tid & 31;
    const int qt = gridDim.x - 1 - blockIdx.x;    // heavy tiles first
    const int h  = blockIdx.y;
    const int b  = blockIdx.z;
    const int nkt = 2 * qt + 2;
    const size_t tok0 = (size_t)b * SEQ;

    for (int i = tid; i < 128 * 8; i += 256) {
        const int row = i >> 3, seg = i & 7;
        const size_t goff = (tok0 + qt * 128 + row) * D_MODEL + h * 64 + seg * 8;
        const uint32_t soff = row * KSTR + seg * 16;
        cp_async16(sQh + soff, g_qh + goff);
        cp_async16(sQl + soff, g_ql + goff);
    }
    auto kvbase = [&](int s) { return sb + 2 * QTILE_B + s * KVSTAGE_B; };
    auto loadKV = [&](int kt, int s) {
        const uint32_t base = kvbase(s);
        const int seg = tid & 7, r = tid >> 3;
        const int j0 = kt * 64;
#pragma unroll
        for (int rr2 = 0; rr2 < 2; rr2++) {
            const int row = r + rr2 * 32;
            const size_t goff = (tok0 + j0 + row) * D_MODEL + h * 64 + seg * 8;
            const uint32_t soff = row * KSTR + seg * 16;
            cp_async16(base + 0 * KVTILE_B + soff, g_k + goff);
            cp_async16(base + 1 * KVTILE_B + soff, g_v + goff);
        }
    };
    loadKV(0, 0);
    CP_COMMIT();
    CP_WAIT0();
    __syncthreads();

    uint32_t qhf[4][4], qlf[4][4];
    {
        const uint32_t aoff = (wid * 16 + (lane & 15)) * KSTR + (lane >> 4) * 16;
#pragma unroll
        for (int ka = 0; ka < 4; ka++) {
            ldm_x4(qhf[ka], sQh + aoff + ka * 32);
            ldm_x4(qlf[ka], sQl + aoff + ka * 32);
        }
    }

    float o[8][4];
#pragma unroll
    for (int f = 0; f < 8; f++)
#pragma unroll
        for (int k = 0; k < 4; k++) o[f][k] = 0.0f;
    float m0f = -1e30f, m1f = -1e30f, l0 = 0.0f, l1 = 0.0f;

    const int rmin = qt * 128 + wid * 16;
    const int g8 = lane >> 3;
    const uint32_t boffB = ((g8 >> 1) * 8 + (lane & 7)) * KSTR + (g8 & 1) * 16;
    const uint32_t voffB = (lane & 15) * KSTR + (lane >> 4) * 16;
    const int t2 = lane & 3, gq = lane >> 2;

    for (int kt = 0; kt < nkt; kt++) {
        const int s = kt & 1;
        if (kt + 1 < nkt) { loadKV(kt + 1, s ^ 1); CP_COMMIT(); }
        const uint32_t bK = kvbase(s);
        const int j0 = kt * 64;
        const bool activew = (j0 <= rmin + 15);

        if (activew) {
            float sacc[8][4];
#pragma unroll
            for (int f = 0; f < 8; f++)
#pragma unroll
                for (int k = 0; k < 4; k++) sacc[f][k] = 0.0f;

            // ---- S = (Qh+Ql) K^T : 2 terms ----
#pragma unroll
            for (int ka = 0; ka < 4; ka++) {
                uint32_t kb[4][4];
#pragma unroll
                for (int nf16 = 0; nf16 < 4; nf16++)
                    ldm_x4(kb[nf16], bK + nf16 * (16 * KSTR) + boffB + ka * 32);
#pragma unroll
                for (int nf16 = 0; nf16 < 4; nf16++)
#pragma unroll
                    for (int h2 = 0; h2 < 2; h2++)
                        mma_f16(sacc[nf16 * 2 + h2], qhf[ka],
                                kb[nf16][h2 * 2], kb[nf16][h2 * 2 + 1]);
#pragma unroll
                for (int nf16 = 0; nf16 < 4; nf16++)
#pragma unroll
                    for (int h2 = 0; h2 < 2; h2++)
                        mma_f16(sacc[nf16 * 2 + h2], qlf[ka],
                                kb[nf16][h2 * 2], kb[nf16][h2 * 2 + 1]);
            }

            // ---- causal mask (diagonal tiles only) ----
            const int row0 = rmin + gq, row1 = row0 + 8;
            if (j0 + 63 > rmin) {
#pragma unroll
                for (int f = 0; f < 8; f++) {
                    const int cbase = j0 + f * 8 + t2 * 2;
                    if (cbase     > row0) sacc[f][0] = -1e30f;
                    if (cbase + 1 > row0) sacc[f][1] = -1e30f;
                    if (cbase     > row1) sacc[f][2] = -1e30f;
                    if (cbase + 1 > row1) sacc[f][3] = -1e30f;
                }
            }

            // ---- online softmax (rows gq, gq+8) ----
            float mx0 = -1e30f, mx1 = -1e30f;
#pragma unroll
            for (int f = 0; f < 8; f++) {
                mx0 = fmaxf(mx0, fmaxf(sacc[f][0], sacc[f][1]));
                mx1 = fmaxf(mx1, fmaxf(sacc[f][2], sacc[f][3]));
            }
#pragma unroll
            for (int off = 1; off < 4; off <<= 1) {
                mx0 = fmaxf(mx0, __shfl_xor_sync(0xffffffffu, mx0, off));
                mx1 = fmaxf(mx1, __shfl_xor_sync(0xffffffffu, mx1, off));
            }
            const float mn0 = fmaxf(m0f, mx0), mn1 = fmaxf(m1f, mx1);
            const float al0 = ex2f((m0f - mn0) * SCL);
            const float al1 = ex2f((m1f - mn1) * SCL);
            m0f = mn0; m1f = mn1;
            float sum0 = 0.0f, sum1 = 0.0f;
#pragma unroll
            for (int f = 0; f < 8; f++) {
                sacc[f][0] = ex2f((sacc[f][0] - mn0) * SCL);
                sacc[f][1] = ex2f((sacc[f][1] - mn0) * SCL);
                sacc[f][2] = ex2f((sacc[f][2] - mn1) * SCL);
                sacc[f][3] = ex2f((sacc[f][3] - mn1) * SCL);
                sum0 += sacc[f][0] + sacc[f][1];
                sum1 += sacc[f][2] + sacc[f][3];
            }
#pragma unroll
            for (int off = 1; off < 4; off <<= 1) {
                sum0 += __shfl_xor_sync(0xffffffffu, sum0, off);
                sum1 += __shfl_xor_sync(0xffffffffu, sum1, off);
            }
            l0 = l0 * al0 + sum0;
            l1 = l1 * al1 + sum1;
#pragma unroll
            for (int f = 0; f < 8; f++) {
                o[f][0] *= al0; o[f][1] *= al0;
                o[f][2] *= al1; o[f][3] *= al1;
            }

            // ---- O += P V : 1 term ----
#pragma unroll
            for (int kj = 0; kj < 4; kj++) {
                uint32_t ph[4];
                {
                    const float* pa = sacc[2 * kj];
                    const float* pb = sacc[2 * kj + 1];
                    ph[0] = pk_f16(pa[0], pa[1]); ph[1] = pk_f16(pa[2], pa[3]);
                    ph[2] = pk_f16(pb[0], pb[1]); ph[3] = pk_f16(pb[2], pb[3]);
                }
                uint32_t vb[4][4];
#pragma unroll
                for (int nf16 = 0; nf16 < 4; nf16++)
                    ldm_x4_trans(vb[nf16],
                                 bK + KVTILE_B + kj * (16 * KSTR) + voffB + nf16 * 32);
#pragma unroll
                for (int nf16 = 0; nf16 < 4; nf16++)
#pragma unroll
                    for (int h2 = 0; h2 < 2; h2++)
                        mma_f16(o[nf16 * 2 + h2], ph,
                                vb[nf16][h2 * 2], vb[nf16][h2 * 2 + 1]);
            }
        }
        if (kt + 1 < nkt) CP_WAIT0();
        __syncthreads();
    }

    // ---- normalize + single-fp16 store of ctx ----
    const float inv0 = 1.0f / l0, inv1 = 1.0f / l1;
    const size_t row0 = tok0 + qt * 128 + wid * 16 + gq;
#pragma unroll
    for (int f = 0; f < 8; f++) {
        const int col = h * 64 + f * 8 + t2 * 2;
        *(__half2*)(g_ch + row0 * D_MODEL + col) =
            __floats2half2_rn(o[f][0] * inv0, o[f][1] * inv0);
        *(__half2*)(g_ch + (row0 + 8) * D_MODEL + col) =
            __floats2half2_rn(o[f][2] * inv1, o[f][3] * inv1);
    }
}

// ---------------- launch ----------------
extern "C" void kernel_launch(void* const* d_in, const int* in_sizes, int n_in,
                              void* d_out, int out_size) {
    (void)in_sizes; (void)n_in; (void)out_size;
    const float* x  = (const float*)d_in[0];
    const float* Wq = (const float*)d_in[1];
    const float* Wk = (const float*)d_in[2];
    const float* Wv = (const float*)d_in[3];
    const float* Wo = (const float*)d_in[4];
    float* out = (float*)d_out;

    __half *xh, *xl, *w, *qh, *ql, *k, *v, *ch;
    cudaGetSymbolAddress((void**)&xh, g_xh);
    cudaGetSymbolAddress((void**)&xl, g_xl);
    cudaGetSymbolAddress((void**)&w,  g_w);
    cudaGetSymbolAddress((void**)&qh, g_qh);
    cudaGetSymbolAddress((void**)&ql, g_ql);
    cudaGetSymbolAddress((void**)&k,  g_k);
    cudaGetSymbolAddress((void**)&v,  g_v);
    cudaGetSymbolAddress((void**)&ch, g_ch);

    cvt_all<<<dim3(M_TOT * D_MODEL / 4 / 256, 5), 256>>>(x, Wq, Wk, Wv, Wo);

    cudaFuncSetAttribute(gemm_tc, cudaFuncAttributeMaxDynamicSharedMemorySize, GEMM_SMEM);
    cudaFuncSetAttribute(flash_tc, cudaFuncAttributeMaxDynamicSharedMemorySize, FLASH_SMEM);

    // QKV: z=0 -> q (2-term, split out), z=1 -> k (1-term, single), z=2 -> v (1-term)
    gemm_tc<<<dim3(8, 32, 3), 256, GEMM_SMEM>>>(xh, xl, w, nullptr,
                                                qh, ql, k, nullptr, v, nullptr);
    flash_tc<<<dim3(SEQ / 128, NH, BATCH), 256, FLASH_SMEM>>>();
    // out projection: ctx single-term x Wo -> fp32 out
    gemm_tc<<<dim3(8, 32, 1), 256, GEMM_SMEM>>>(ch, nullptr, w + 3 * MM, out,
                                                nullptr, nullptr, nullptr, nullptr,
                                                nullptr, nullptr);
}

// round 17
// speedup vs baseline: 1.0978x; 1.0978x over previous
#include <cuda_runtime.h>
#include <cuda_fp16.h>
#include <cstdint>
#include <math.h>

#define D_MODEL 1024
#define NH      16
#define DK      64
#define BATCH   2
#define SEQ     2048
#define M_TOT   (BATCH * SEQ)   // 4096
#define MM      (D_MODEL * D_MODEL)

// ---------------- scratch (static device memory; no allocations) ----------------
__device__ __half g_xh[M_TOT * D_MODEL];   // x split hi
__device__ __half g_xl[M_TOT * D_MODEL];   // x split lo
__device__ __half g_w [4 * MM];            // weights, single fp16
__device__ __half g_qh[M_TOT * D_MODEL];   // q split
__device__ __half g_ql[M_TOT * D_MODEL];
__device__ __half g_k [M_TOT * D_MODEL];   // k single
__device__ __half g_v [M_TOT * D_MODEL];   // v single
__device__ __half g_ch[M_TOT * D_MODEL];   // ctx single

// ================= helpers =================
static __device__ __forceinline__ uint32_t smem_to_u32(const void* p) {
    uint32_t a;
    asm("{ .reg .u64 t; cvta.to.shared.u64 t, %1; cvt.u32.u64 %0, t; }" : "=r"(a) : "l"(p));
    return a;
}
static __device__ __forceinline__ void cp_async16(uint32_t saddr, const void* gaddr) {
    asm volatile("cp.async.cg.shared.global [%0], [%1], 16;" :: "r"(saddr), "l"(gaddr));
}
#define CP_COMMIT() asm volatile("cp.async.commit_group;" ::: "memory")
#define CP_WAIT0()  asm volatile("cp.async.wait_group 0;" ::: "memory")

static __device__ __forceinline__ void ldm_x4(uint32_t* r, uint32_t addr) {
    asm volatile("ldmatrix.sync.aligned.m8n8.x4.shared.b16 {%0,%1,%2,%3}, [%4];"
                 : "=r"(r[0]), "=r"(r[1]), "=r"(r[2]), "=r"(r[3]) : "r"(addr));
}
static __device__ __forceinline__ void ldm_x4_trans(uint32_t* r, uint32_t addr) {
    asm volatile("ldmatrix.sync.aligned.m8n8.x4.trans.shared.b16 {%0,%1,%2,%3}, [%4];"
                 : "=r"(r[0]), "=r"(r[1]), "=r"(r[2]), "=r"(r[3]) : "r"(addr));
}
static __device__ __forceinline__ void mma_f16(float* d, const uint32_t* a,
                                               uint32_t b0, uint32_t b1) {
    asm volatile(
        "mma.sync.aligned.m16n8k16.row.col.f32.f16.f16.f32 "
        "{%0,%1,%2,%3}, {%4,%5,%6,%7}, {%8,%9}, {%0,%1,%2,%3};"
        : "+f"(d[0]), "+f"(d[1]), "+f"(d[2]), "+f"(d[3])
        : "r"(a[0]), "r"(a[1]), "r"(a[2]), "r"(a[3]), "r"(b0), "r"(b1));
}
static __device__ __forceinline__ float ex2f(float x) {
    float r;
    asm("ex2.approx.ftz.f32 %0, %1;" : "=f"(r) : "f"(x));
    return r;
}
static __device__ __forceinline__ uint32_t pk_f16(float x, float y) {
    __half2 t = __floats2half2_rn(x, y);
    return *(uint32_t*)&t;
}

// ================= fused convert: W -> fp16 single; x -> fp16 split ==========
__global__ void __launch_bounds__(256) cvt_all(const float* __restrict__ x,
                                               const float* __restrict__ Wq,
                                               const float* __restrict__ Wk,
                                               const float* __restrict__ Wv,
                                               const float* __restrict__ Wo) {
    const int y = blockIdx.y;
    int i = (blockIdx.x * 256 + threadIdx.x) * 4;
    if (y < 4) {
        if (i >= MM) return;
        const float* src = (y == 0) ? Wq : (y == 1) ? Wk : (y == 2) ? Wv : Wo;
        __half* w = g_w + (size_t)y * MM;
        float4 v = *(const float4*)(src + i);
        *(__half2*)(w + i)     = __floats2half2_rn(v.x, v.y);
        *(__half2*)(w + i + 2) = __floats2half2_rn(v.z, v.w);
    } else {
        if (i >= M_TOT * D_MODEL) return;
        float4 v = *(const float4*)(x + i);
        __half h0 = __float2half_rn(v.x), h1 = __float2half_rn(v.y);
        __half h2 = __float2half_rn(v.z), h3 = __float2half_rn(v.w);
        *(__half2*)(g_xh + i)     = __half2(h0, h1);
        *(__half2*)(g_xh + i + 2) = __half2(h2, h3);
        *(__half2*)(g_xl + i) = __floats2half2_rn(v.x - __half2float(h0),
                                                  v.y - __half2float(h1));
        *(__half2*)(g_xl + i + 2) = __floats2half2_rn(v.z - __half2float(h2),
                                                      v.w - __half2float(h3));
    }
}

// ================= HMMA fp16 GEMM: 2-term when AlOpt, else 1-term ============
// K-chunks of 64 (NCHUNK 16); rows at 144B stride (conflict-free ldmatrix/STS).
// smem 110592 B/CTA; 2 CTAs/SM (221184 <= 227KB carveout).
#define TSTRIDE_B 144
#define TILE_B    (128 * TSTRIDE_B)      // 18432
#define STAGE_B   (3 * TILE_B)           // 55296: Ah, Al, W
#define GEMM_SMEM (2 * STAGE_B)          // 110592
#define NCHUNK    16

__global__ void __launch_bounds__(256, 2)
gemm_tc(const __half* __restrict__ Ah, const __half* __restrict__ AlOpt,
        const __half* __restrict__ W0,
        float* Cf,
        __half* H0, __half* L0,
        __half* H1, __half* L1,
        __half* H2, __half* L2) {
    extern __shared__ char smem[];
    const uint32_t sb = smem_to_u32(smem);
    const int tid  = threadIdx.x;
    const int wid  = tid >> 5;
    const int lane = tid & 31;
    const int z  = blockIdx.z;
    const int m0 = blockIdx.y * 128;
    const int n0 = blockIdx.x * 128;

    // lo term only on the q path (z==0); k/v/out-proj are 1-term
    const __half* Al = (z == 0) ? AlOpt : nullptr;
    const __half* Wz = W0 + (size_t)z * MM;
    __half* Hz = (z == 0) ? H0 : (z == 1) ? H1 : H2;
    __half* Lz = (z == 0) ? L0 : (z == 1) ? L1 : L2;

    const int seg = tid & 7;     // 16B segment within 128B row
    const int r0  = tid >> 3;    // 0..31

    auto load_chunk = [&](int kc, int s) {
        const uint32_t sbase = sb + s * STAGE_B;
        const int ke = kc * 64 + seg * 8;
#pragma unroll
        for (int j = 0; j < 4; j++) {
            const int row = r0 + j * 32;
            const uint32_t soff = row * TSTRIDE_B + seg * 16;
            cp_async16(sbase + 0 * TILE_B + soff, Ah + (size_t)(m0 + row) * D_MODEL + ke);
            if (Al)
                cp_async16(sbase + 1 * TILE_B + soff, Al + (size_t)(m0 + row) * D_MODEL + ke);
            cp_async16(sbase + 2 * TILE_B + soff, Wz + (size_t)(n0 + row) * D_MODEL + ke);
        }
    };

    const int wm = wid >> 2;
    const int wn = wid & 3;
    const uint32_t aRowOff = (uint32_t)((wm * 64 + (lane & 15)) * TSTRIDE_B + (lane >> 4) * 16);
    const int g = lane >> 3;
    const uint32_t bRowOff = (uint32_t)((wn * 32 + (g >> 1) * 8 + (lane & 7)) * TSTRIDE_B + (g & 1) * 16);

    float acc[4][4][4];
#pragma unroll
    for (int i = 0; i < 4; i++)
#pragma unroll
        for (int j = 0; j < 4; j++)
#pragma unroll
            for (int k = 0; k < 4; k++) acc[i][j][k] = 0.0f;

    load_chunk(0, 0);
    CP_COMMIT();

    for (int c = 0; c < NCHUNK; c++) {
        const int s = c & 1;
        CP_WAIT0();
        __syncthreads();
        if (c + 1 < NCHUNK) { load_chunk(c + 1, s ^ 1); CP_COMMIT(); }

        const uint32_t stage = sb + s * STAGE_B;
        const uint32_t ahB = stage + aRowOff;
        const uint32_t alB = ahB + TILE_B;
        const uint32_t wB  = stage + 2 * TILE_B + bRowOff;

#pragma unroll
        for (int kk = 0; kk < 4; kk++) {
            const uint32_t ka = kk * 32;
            uint32_t ahf[4][4], whf[2][4];
#pragma unroll
            for (int mf = 0; mf < 4; mf++)
                ldm_x4(ahf[mf], ahB + mf * (16 * TSTRIDE_B) + ka);
#pragma unroll
            for (int p = 0; p < 2; p++)
                ldm_x4(whf[p], wB + p * (16 * TSTRIDE_B) + ka);

#pragma unroll
            for (int mf = 0; mf < 4; mf++)
#pragma unroll
                for (int nf = 0; nf < 4; nf++) {
                    const int p = nf >> 1, h = (nf & 1) * 2;
                    mma_f16(acc[mf][nf], ahf[mf], whf[p][h], whf[p][h + 1]);
                }
            if (Al) {
                uint32_t alf[4][4];
#pragma unroll
                for (int mf = 0; mf < 4; mf++)
                    ldm_x4(alf[mf], alB + mf * (16 * TSTRIDE_B) + ka);
#pragma unroll
                for (int mf = 0; mf < 4; mf++)
#pragma unroll
                    for (int nf = 0; nf < 4; nf++) {
                        const int p = nf >> 1, h = (nf & 1) * 2;
                        mma_f16(acc[mf][nf], alf[mf], whf[p][h], whf[p][h + 1]);
                    }
            }
        }
        __syncthreads();
    }

    const int rr = lane >> 2;
    const int cc = (lane & 3) * 2;
#pragma unroll
    for (int mf = 0; mf < 4; mf++) {
#pragma unroll
        for (int nf = 0; nf < 4; nf++) {
            const size_t row = (size_t)(m0 + wm * 64 + mf * 16 + rr);
            const int col = n0 + wn * 32 + nf * 8 + cc;
            if (Cf) {
                float* cp = Cf + row * D_MODEL + col;
                *(float2*)cp                 = make_float2(acc[mf][nf][0], acc[mf][nf][1]);
                *(float2*)(cp + 8 * D_MODEL) = make_float2(acc[mf][nf][2], acc[mf][nf][3]);
            } else if (Lz) {   // split fp16 output (q)
#pragma unroll
                for (int hh = 0; hh < 2; hh++) {
                    float a0 = acc[mf][nf][hh * 2 + 0];
                    float a1 = acc[mf][nf][hh * 2 + 1];
                    __half h0 = __float2half_rn(a0);
                    __half h1 = __float2half_rn(a1);
                    size_t off = (row + hh * 8) * D_MODEL + col;
                    *(__half2*)(Hz + off) = __half2(h0, h1);
                    *(__half2*)(Lz + off) = __floats2half2_rn(a0 - __half2float(h0),
                                                              a1 - __half2float(h1));
                }
            } else {            // single fp16 output (k, v)
#pragma unroll
                for (int hh = 0; hh < 2; hh++) {
                    size_t off = (row + hh * 8) * D_MODEL + col;
                    *(__half2*)(Hz + off) = __floats2half2_rn(acc[mf][nf][hh * 2 + 0],
                                                              acc[mf][nf][hh * 2 + 1]);
                }
            }
        }
    }
}

// ================= HMMA flash attention (Q 2-term, P 1-term, causal) =========
#define KSTR 144
#define QTILE_B  (128 * KSTR)
#define KVTILE_B (64 * KSTR)
#define KVSTAGE_B (2 * KVTILE_B)        // K, V
#define FLASH_SMEM (2 * QTILE_B + 2 * KVSTAGE_B)   // 73728
#define SCL 0.18033688f                 // 0.125 * log2(e)

__global__ void __launch_bounds__(256, 1) flash_tc() {
    extern __shared__ char smf[];
    const uint32_t sb = smem_to_u32(smf);
    const uint32_t sQh = sb;
    const uint32_t sQl = sb + QTILE_B;
    const int tid  = threadIdx.x;
    const int wid  = tid >> 5;
    const int lane = tid & 31;
    const int qt = gridDim.x - 1 - blockIdx.x;    // heavy tiles first
    const int h  = blockIdx.y;
    const int b  = blockIdx.z;
    const int nkt = 2 * qt + 2;
    const size_t tok0 = (size_t)b * SEQ;

    for (int i = tid; i < 128 * 8; i += 256) {
        const int row = i >> 3, seg = i & 7;
        const size_t goff = (tok0 + qt * 128 + row) * D_MODEL + h * 64 + seg * 8;
        const uint32_t soff = row * KSTR + seg * 16;
        cp_async16(sQh + soff, g_qh + goff);
        cp_async16(sQl + soff, g_ql + goff);
    }
    auto kvbase = [&](int s) { return sb + 2 * QTILE_B + s * KVSTAGE_B; };
    auto loadKV = [&](int kt, int s) {
        const uint32_t base = kvbase(s);
        const int seg = tid & 7, r = tid >> 3;
        const int j0 = kt * 64;
#pragma unroll
        for (int rr2 = 0; rr2 < 2; rr2++) {
            const int row = r + rr2 * 32;
            const size_t goff = (tok0 + j0 + row) * D_MODEL + h * 64 + seg * 8;
            const uint32_t soff = row * KSTR + seg * 16;
            cp_async16(base + 0 * KVTILE_B + soff, g_k + goff);
            cp_async16(base + 1 * KVTILE_B + soff, g_v + goff);
        }
    };
    loadKV(0, 0);
    CP_COMMIT();
    CP_WAIT0();
    __syncthreads();

    uint32_t qhf[4][4], qlf[4][4];
    {
        const uint32_t aoff = (wid * 16 + (lane & 15)) * KSTR + (lane >> 4) * 16;
#pragma unroll
        for (int ka = 0; ka < 4; ka++) {
            ldm_x4(qhf[ka], sQh + aoff + ka * 32);
            ldm_x4(qlf[ka], sQl + aoff + ka * 32);
        }
    }

    float o[8][4];
#pragma unroll
    for (int f = 0; f < 8; f++)
#pragma unroll
        for (int k = 0; k < 4; k++) o[f][k] = 0.0f;
    float m0f = -1e30f, m1f = -1e30f, l0 = 0.0f, l1 = 0.0f;

    const int rmin = qt * 128 + wid * 16;
    const int g8 = lane >> 3;
    const uint32_t boffB = ((g8 >> 1) * 8 + (lane & 7)) * KSTR + (g8 & 1) * 16;
    const uint32_t voffB = (lane & 15) * KSTR + (lane >> 4) * 16;
    const int t2 = lane & 3, gq = lane >> 2;

    for (int kt = 0; kt < nkt; kt++) {
        const int s = kt & 1;
        if (kt + 1 < nkt) { loadKV(kt + 1, s ^ 1); CP_COMMIT(); }
        const uint32_t bK = kvbase(s);
        const int j0 = kt * 64;
        const bool activew = (j0 <= rmin + 15);

        if (activew) {
            float sacc[8][4];
#pragma unroll
            for (int f = 0; f < 8; f++)
#pragma unroll
                for (int k = 0; k < 4; k++) sacc[f][k] = 0.0f;

            // ---- S = (Qh+Ql) K^T : 2 terms ----
#pragma unroll
            for (int ka = 0; ka < 4; ka++) {
                uint32_t kb[4][4];
#pragma unroll
                for (int nf16 = 0; nf16 < 4; nf16++)
                    ldm_x4(kb[nf16], bK + nf16 * (16 * KSTR) + boffB + ka * 32);
#pragma unroll
                for (int nf16 = 0; nf16 < 4; nf16++)
#pragma unroll
                    for (int h2 = 0; h2 < 2; h2++)
                        mma_f16(sacc[nf16 * 2 + h2], qhf[ka],
                                kb[nf16][h2 * 2], kb[nf16][h2 * 2 + 1]);
#pragma unroll
                for (int nf16 = 0; nf16 < 4; nf16++)
#pragma unroll
                    for (int h2 = 0; h2 < 2; h2++)
                        mma_f16(sacc[nf16 * 2 + h2], qlf[ka],
                                kb[nf16][h2 * 2], kb[nf16][h2 * 2 + 1]);
            }

            // ---- causal mask (diagonal tiles only) ----
            const int row0 = rmin + gq, row1 = row0 + 8;
            if (j0 + 63 > rmin) {
#pragma unroll
                for (int f = 0; f < 8; f++) {
                    const int cbase = j0 + f * 8 + t2 * 2;
                    if (cbase     > row0) sacc[f][0] = -1e30f;
                    if (cbase + 1 > row0) sacc[f][1] = -1e30f;
                    if (cbase     > row1) sacc[f][2] = -1e30f;
                    if (cbase + 1 > row1) sacc[f][3] = -1e30f;
                }
            }

            // ---- online softmax (rows gq, gq+8) ----
            float mx0 = -1e30f, mx1 = -1e30f;
#pragma unroll
            for (int f = 0; f < 8; f++) {
                mx0 = fmaxf(mx0, fmaxf(sacc[f][0], sacc[f][1]));
                mx1 = fmaxf(mx1, fmaxf(sacc[f][2], sacc[f][3]));
            }
#pragma unroll
            for (int off = 1; off < 4; off <<= 1) {
                mx0 = fmaxf(mx0, __shfl_xor_sync(0xffffffffu, mx0, off));
                mx1 = fmaxf(mx1, __shfl_xor_sync(0xffffffffu, mx1, off));
            }
            const float mn0 = fmaxf(m0f, mx0), mn1 = fmaxf(m1f, mx1);
            const float al0 = ex2f((m0f - mn0) * SCL);
            const float al1 = ex2f((m1f - mn1) * SCL);
            m0f = mn0; m1f = mn1;
            float sum0 = 0.0f, sum1 = 0.0f;
#pragma unroll
            for (int f = 0; f < 8; f++) {
                sacc[f][0] = ex2f((sacc[f][0] - mn0) * SCL);
                sacc[f][1] = ex2f((sacc[f][1] - mn0) * SCL);
                sacc[f][2] = ex2f((sacc[f][2] - mn1) * SCL);
                sacc[f][3] = ex2f((sacc[f][3] - mn1) * SCL);
                sum0 += sacc[f][0] + sacc[f][1];
                sum1 += sacc[f][2] + sacc[f][3];
            }
#pragma unroll
            for (int off = 1; off < 4; off <<= 1) {
                sum0 += __shfl_xor_sync(0xffffffffu, sum0, off);
                sum1 += __shfl_xor_sync(0xffffffffu, sum1, off);
            }
            l0 = l0 * al0 + sum0;
            l1 = l1 * al1 + sum1;
#pragma unroll
            for (int f = 0; f < 8; f++) {
                o[f][0] *= al0; o[f][1] *= al0;
                o[f][2] *= al1; o[f][3] *= al1;
            }

            // ---- O += P V : 1 term ----
#pragma unroll
            for (int kj = 0; kj < 4; kj++) {
                uint32_t ph[4];
                {
                    const float* pa = sacc[2 * kj];
                    const float* pb = sacc[2 * kj + 1];
                    ph[0] = pk_f16(pa[0], pa[1]); ph[1] = pk_f16(pa[2], pa[3]);
                    ph[2] = pk_f16(pb[0], pb[1]); ph[3] = pk_f16(pb[2], pb[3]);
                }
                uint32_t vb[4][4];
#pragma unroll
                for (int nf16 = 0; nf16 < 4; nf16++)
                    ldm_x4_trans(vb[nf16],
                                 bK + KVTILE_B + kj * (16 * KSTR) + voffB + nf16 * 32);
#pragma unroll
                for (int nf16 = 0; nf16 < 4; nf16++)
#pragma unroll
                    for (int h2 = 0; h2 < 2; h2++)
                        mma_f16(o[nf16 * 2 + h2], ph,
                                vb[nf16][h2 * 2], vb[nf16][h2 * 2 + 1]);
            }
        }
        if (kt + 1 < nkt) CP_WAIT0();
        __syncthreads();
    }

    // ---- normalize + single-fp16 store of ctx ----
    const float inv0 = 1.0f / l0, inv1 = 1.0f / l1;
    const size_t row0 = tok0 + qt * 128 + wid * 16 + gq;
#pragma unroll
    for (int f = 0; f < 8; f++) {
        const int col = h * 64 + f * 8 + t2 * 2;
        *(__half2*)(g_ch + row0 * D_MODEL + col) =
            __floats2half2_rn(o[f][0] * inv0, o[f][1] * inv0);
        *(__half2*)(g_ch + (row0 + 8) * D_MODEL + col) =
            __floats2half2_rn(o[f][2] * inv1, o[f][3] * inv1);
    }
}

// ---------------- launch ----------------
extern "C" void kernel_launch(void* const* d_in, const int* in_sizes, int n_in,
                              void* d_out, int out_size) {
    (void)in_sizes; (void)n_in; (void)out_size;
    const float* x  = (const float*)d_in[0];
    const float* Wq = (const float*)d_in[1];
    const float* Wk = (const float*)d_in[2];
    const float* Wv = (const float*)d_in[3];
    const float* Wo = (const float*)d_in[4];
    float* out = (float*)d_out;

    __half *xh, *xl, *w, *qh, *ql, *k, *v, *ch;
    cudaGetSymbolAddress((void**)&xh, g_xh);
    cudaGetSymbolAddress((void**)&xl, g_xl);
    cudaGetSymbolAddress((void**)&w,  g_w);
    cudaGetSymbolAddress((void**)&qh, g_qh);
    cudaGetSymbolAddress((void**)&ql, g_ql);
    cudaGetSymbolAddress((void**)&k,  g_k);
    cudaGetSymbolAddress((void**)&v,  g_v);
    cudaGetSymbolAddress((void**)&ch, g_ch);

    cvt_all<<<dim3(M_TOT * D_MODEL / 4 / 256, 5), 256>>>(x, Wq, Wk, Wv, Wo);

    cudaFuncSetAttribute(gemm_tc, cudaFuncAttributeMaxDynamicSharedMemorySize, GEMM_SMEM);
    cudaFuncSetAttribute(flash_tc, cudaFuncAttributeMaxDynamicSharedMemorySize, FLASH_SMEM);

    // QKV: z=0 -> q (2-term, split out), z=1 -> k (1-term, single), z=2 -> v (1-term)
    gemm_tc<<<dim3(8, 32, 3), 256, GEMM_SMEM>>>(xh, xl, w, nullptr,
                                                qh, ql, k, nullptr, v, nullptr);
    flash_tc<<<dim3(SEQ / 128, NH, BATCH), 256, FLASH_SMEM>>>();
    // out projection: ctx single-term x Wo -> fp32 out
    gemm_tc<<<dim3(8, 32, 1), 256, GEMM_SMEM>>>(ch, nullptr, w + 3 * MM, out,
                                                nullptr, nullptr, nullptr, nullptr,
                                                nullptr, nullptr);
}